// round 10
// baseline (speedup 1.0000x reference)
#include <cuda_runtime.h>
#include <cstddef>
#include <cstdint>

#define LAYERS 5
#define H 128
#define T 2048
#define BATCH 256
#define G 29           // batch groups per layer (grid = 145)
#define BG 9           // rows per group (s0: rows 0-4, s1: rows 5-8)
#define BPAD 264       // padded batch rows in staging buffer
#define NTH 512
#define KS 8           // k-slices
#define KPER 16        // k rows per slice
#define CHUNK 8        // flag publish granularity

typedef unsigned long long ull;

__device__ float Xbuf[(size_t)(LAYERS - 1) * T * BPAD * H];
__device__ int progressFlag[LAYERS * G];

__device__ __forceinline__ ull pack2(float lo, float hi) {
    ull r; asm("mov.b64 %0,{%1,%2};" : "=l"(r) : "f"(lo), "f"(hi)); return r;
}
__device__ __forceinline__ void fma2(ull& acc, ull a, ull b) {
    asm("fma.rn.f32x2 %0,%1,%2,%0;" : "+l"(acc) : "l"(a), "l"(b));
}
__device__ __forceinline__ float lo_of(ull v) {
    return __uint_as_float((unsigned)(v & 0xffffffffull));
}
__device__ __forceinline__ float fast_sigmoid(float x) {
    return 1.0f / (1.0f + __expf(-x));
}
__device__ __forceinline__ int ld_acquire(const int* p) {
    int v; asm volatile("ld.acquire.gpu.s32 %0,[%1];" : "=r"(v) : "l"(p) : "memory"); return v;
}
__device__ __forceinline__ void st_release(int* p, int v) {
    asm volatile("st.release.gpu.s32 [%0],%1;" :: "l"(p), "r"(v) : "memory");
}

struct Smem {
    float partA[KS][3][BG][H];     // 110.6 KB
    float partB[KS][BG][H];        //  36.9 KB
    ulonglong2 hx[BG][H];          //  18.4 KB  {h,h | x,x}
    ull   rh2[BG][H];              //   9.2 KB
    float zbuf[BG][H];             //   4.6 KB
    float preh[BG][H];             //   4.6 KB
    float br[H];
    float bz[H];
    float bh_[H];
    int   avail_sh;
};                                 // ~186 KB

struct Ctx {
    const float* whr; const float* wxr; const float* whz;
    const float* wxz; const float* wxh; const float* whh;
    const float* inp; const float* xsrc; float* ysnk; float* out;
    int l, row0, tid, j0, ks, k0;
};

// -------- phase templates (BOFF = first row of sub-group, NB = rows) --------

template<int BOFF, int NB>
__device__ __forceinline__ void stageA_sub(Smem& sm, const Ctx& c) {
    ull ar[NB], az[NB], ax[NB];
    #pragma unroll
    for (int b = 0; b < NB; ++b) { ar[b] = 0ull; az[b] = 0ull; ax[b] = 0ull; }
    #pragma unroll 2
    for (int kk = 0; kk < KPER; ++kk) {
        const int k = c.k0 + kk;
        const ull w1 = __ldg(reinterpret_cast<const ull*>(c.whr + k * H + c.j0));
        const ull w2 = __ldg(reinterpret_cast<const ull*>(c.wxr + k * H + c.j0));
        const ull w3 = __ldg(reinterpret_cast<const ull*>(c.whz + k * H + c.j0));
        const ull w4 = __ldg(reinterpret_cast<const ull*>(c.wxz + k * H + c.j0));
        const ull w5 = __ldg(reinterpret_cast<const ull*>(c.wxh + k * H + c.j0));
        #pragma unroll
        for (int b = 0; b < NB; ++b) {
            const ulonglong2 hxv = sm.hx[BOFF + b][k];   // LDS.128 broadcast
            fma2(ar[b], w1, hxv.x);
            fma2(ar[b], w2, hxv.y);
            fma2(az[b], w3, hxv.x);
            fma2(az[b], w4, hxv.y);
            fma2(ax[b], w5, hxv.y);
        }
    }
    #pragma unroll
    for (int b = 0; b < NB; ++b) {
        *reinterpret_cast<ull*>(&sm.partA[c.ks][0][BOFF + b][c.j0]) = ar[b];
        *reinterpret_cast<ull*>(&sm.partA[c.ks][1][BOFF + b][c.j0]) = az[b];
        *reinterpret_cast<ull*>(&sm.partA[c.ks][2][BOFF + b][c.j0]) = ax[b];
    }
}

template<int BOFF, int NB>
__device__ __forceinline__ void combineA_sub(Smem& sm, const Ctx& c) {
    for (int i = c.tid; i < 3 * NB * H; i += NTH) {
        const int g3 = i / (NB * H);
        const int r  = i % (NB * H);
        const int b  = BOFF + (r >> 7);
        const int j  = r & 127;
        float ssum = 0.f;
        #pragma unroll
        for (int ss = 0; ss < KS; ++ss) ssum += sm.partA[ss][g3][b][j];
        if (g3 == 0) {
            const float R  = fast_sigmoid(ssum + sm.br[j]);
            const float rv = R * lo_of(sm.hx[b][j].x);
            sm.rh2[b][j] = pack2(rv, rv);
        } else if (g3 == 1) {
            sm.zbuf[b][j] = fast_sigmoid(ssum + sm.bz[j]);
        } else {
            sm.preh[b][j] = ssum + sm.bh_[j];
        }
    }
}

template<int BOFF, int NB>
__device__ __forceinline__ void stageB_sub(Smem& sm, const Ctx& c) {
    ull bh[NB];
    #pragma unroll
    for (int b = 0; b < NB; ++b) bh[b] = 0ull;
    #pragma unroll 4
    for (int kk = 0; kk < KPER; ++kk) {
        const int k = c.k0 + kk;
        const ull w = __ldg(reinterpret_cast<const ull*>(c.whh + k * H + c.j0));
        #pragma unroll
        for (int b = 0; b < NB; ++b)
            fma2(bh[b], w, sm.rh2[BOFF + b][k]);         // LDS.64 broadcast
    }
    #pragma unroll
    for (int b = 0; b < NB; ++b)
        *reinterpret_cast<ull*>(&sm.partB[c.ks][BOFF + b][c.j0]) = bh[b];
}

template<int BOFF, int NB>
__device__ __forceinline__ void combineB_sub(Smem& sm, const Ctx& c, int t) {
    for (int i = c.tid; i < NB * H; i += NTH) {
        const int b = BOFF + (i >> 7);
        const int j = i & 127;
        float ssum = 0.f;
        #pragma unroll
        for (int ss = 0; ss < KS; ++ss) ssum += sm.partB[ss][b][j];
        const float htld = tanhf(ssum + sm.preh[b][j]);
        const float Z    = sm.zbuf[b][j];
        const float hv   = lo_of(sm.hx[b][j].x);
        const float hn   = Z * htld + (1.0f - Z) * hv;
        sm.hx[b][j].x = pack2(hn, hn);
        const int row = c.row0 + b;
        if (c.l == LAYERS - 1) {
            if (row < BATCH)
                c.out[((size_t)row * T + t) * H + j] = hn;
        } else {
            c.ysnk[((size_t)t * BPAD + row) * H + j] = hn;
        }
    }
}

template<int BOFF, int NB>
__device__ __forceinline__ void xload_sub(Smem& sm, const Ctx& c, int t) {
    for (int i = c.tid; i < NB * H; i += NTH) {
        const int b = BOFF + (i >> 7);
        const int k = i & 127;
        const int row = c.row0 + b;
        float v;
        if (c.l == 0) {
            v = (row < BATCH) ? c.inp[((size_t)row * T + t) * H + k] : 0.0f;
        } else {
            v = c.xsrc[((size_t)t * BPAD + row) * H + k];
        }
        sm.hx[b][k].y = pack2(v, v);
    }
}

__global__ void reset_kernel() {
    int i = threadIdx.x;
    if (i < LAYERS * G) progressFlag[i] = 0;
}

__global__ __launch_bounds__(NTH, 1)
void gru_layer_kernel(
    const float* __restrict__ inp,
    const float* __restrict__ W_hr, const float* __restrict__ W_xr, const float* __restrict__ b_r,
    const float* __restrict__ W_hz, const float* __restrict__ W_xz, const float* __restrict__ b_z,
    const float* __restrict__ W_hh, const float* __restrict__ W_xh, const float* __restrict__ b_h,
    float* __restrict__ out)
{
    extern __shared__ char smem_raw[];
    Smem& sm = *reinterpret_cast<Smem*>(smem_raw);

    const int bid = blockIdx.x;
    const int l   = bid / G;
    const int g   = bid % G;
    const int tid = threadIdx.x;

    Ctx c;
    c.l = l; c.row0 = g * BG; c.tid = tid;
    c.j0 = (tid & 63) << 1;
    c.ks = (tid >> 6) & 7;
    c.k0 = c.ks * KPER;
    c.whr = W_hr + l * H * H;  c.wxr = W_xr + l * H * H;
    c.whz = W_hz + l * H * H;  c.wxz = W_xz + l * H * H;
    c.wxh = W_xh + l * H * H;  c.whh = W_hh + l * H * H;
    c.inp = inp;  c.out = out;
    c.xsrc = (l == 0) ? nullptr : &Xbuf[(size_t)(l - 1) * T * BPAD * H];
    c.ysnk = (l == LAYERS - 1) ? nullptr : &Xbuf[(size_t)l * T * BPAD * H];

    int* myflag  = &progressFlag[l * G + g];
    int* srcflag = (l == 0) ? nullptr : &progressFlag[(l - 1) * G + g];

    // init: h=0 (lo), x=0 (hi), rh2=0, biases
    for (int i = tid; i < BG * H; i += NTH) {
        reinterpret_cast<ulonglong2*>(&sm.hx[0][0])[i] = make_ulonglong2(0ull, 0ull);
        (&sm.rh2[0][0])[i] = 0ull;
    }
    for (int i = tid; i < H; i += NTH) {
        sm.br[i]  = b_r[l * H + i];
        sm.bz[i]  = b_z[l * H + i];
        sm.bh_[i] = b_h[l * H + i];
    }
    __syncthreads();

    int avail = (l == 0) ? T : 0;

    // prologue: x_0 for s0 (needs producer step 0 when l>0)
    if (l > 0 && avail < 1) {
        if (tid == 0) {
            int v = ld_acquire(srcflag);
            while (v < 1) { __nanosleep(200); v = ld_acquire(srcflag); }
            sm.avail_sh = v;
        }
        __syncthreads();
        avail = sm.avail_sh;
    }
    xload_sub<0, 5>(sm, c, 0);
    __syncthreads();

    for (int t = 0; t < T; ++t) {
        // ---- producer wait: need x up to step min(t+1, T-1) available ----
        const int need = (t + 2 < T) ? (t + 2) : T;
        if (l > 0 && avail < need) {
            if (tid == 0) {
                int v = ld_acquire(srcflag);
                while (v < need) { __nanosleep(200); v = ld_acquire(srcflag); }
                sm.avail_sh = v;
            }
            __syncthreads();
            avail = sm.avail_sh;
        }

        // ======== R1: A(s0,t) + CombB(s1,t-1) + xload(s1,t) ========
        stageA_sub<0, 5>(sm, c);
        if (t > 0) combineB_sub<5, 4>(sm, c, t - 1);
        xload_sub<5, 4>(sm, c, t);
        __syncthreads();

        // publish: after CombB(s1,t-1), steps 0..t-1 fully staged
        if (l < LAYERS - 1 && tid == 0 && t > 0 && (t & (CHUNK - 1)) == 0) {
            __threadfence();
            st_release(myflag, t);
        }

        // ======== R2: CombA(s0,t) + A(s1,t) ========
        combineA_sub<0, 5>(sm, c);
        stageA_sub<5, 4>(sm, c);
        __syncthreads();

        // ======== R3: B(s0,t) + CombA(s1,t) ========
        stageB_sub<0, 5>(sm, c);
        combineA_sub<5, 4>(sm, c);
        __syncthreads();

        // ======== R4: CombB(s0,t) + B(s1,t) + xload(s0,t+1) ========
        combineB_sub<0, 5>(sm, c, t);
        stageB_sub<5, 4>(sm, c);
        if (t + 1 < T) xload_sub<0, 5>(sm, c, t + 1);
        __syncthreads();
    }

    // epilogue: finish s1 at T-1, final publish
    combineB_sub<5, 4>(sm, c, T - 1);
    __syncthreads();
    if (l < LAYERS - 1 && tid == 0) {
        __threadfence();
        st_release(myflag, T);
    }
}

extern "C" void kernel_launch(void* const* d_in, const int* in_sizes, int n_in,
                              void* d_out, int out_size) {
    (void)in_sizes; (void)n_in; (void)out_size;
    const float* inp  = (const float*)d_in[0];
    const float* W_hr = (const float*)d_in[1];
    const float* W_xr = (const float*)d_in[2];
    const float* b_r  = (const float*)d_in[3];
    const float* W_hz = (const float*)d_in[4];
    const float* W_xz = (const float*)d_in[5];
    const float* b_z  = (const float*)d_in[6];
    const float* W_hh = (const float*)d_in[7];
    const float* W_xh = (const float*)d_in[8];
    const float* b_h  = (const float*)d_in[9];
    float* out = (float*)d_out;

    reset_kernel<<<1, 256>>>();

    cudaFuncSetAttribute(gru_layer_kernel,
                         cudaFuncAttributeMaxDynamicSharedMemorySize,
                         (int)sizeof(Smem));
    gru_layer_kernel<<<LAYERS * G, NTH, sizeof(Smem)>>>(
        inp, W_hr, W_xr, b_r, W_hz, W_xz, b_z, W_hh, W_xh, b_h, out);
}